// round 11
// baseline (speedup 1.0000x reference)
#include <cuda_runtime.h>
#include <math_constants.h>

// Problem constants (fixed by setup_inputs): B=8, N=128, H=256, F=1023
#define B_ 8
#define N_ 128
#define H_ 256

#define BM 32
#define BN 32
#define BK 128
#define RSTR 132   // row-major tile stride (floats) = 33*16B; with microtile
                   // rows ig+8m / cols jg+8n, frag LDS.128 are conflict-free

// Scratch: per-(row, j-tile) partial argmax + completion counter
__device__ float g_pval[B_ * N_ * 4];
__device__ int   g_pidx[B_ * N_ * 4];
__device__ int   g_cnt;          // zero-initialized; last block resets to 0

// ---------------------------------------------------------------------------
// Fused kernel, 512 threads, 128 blocks (one 32x32 logits tile each).
//   prefetch: each thread LDGs BOTH passes' 16+16 floats of its row up front
//     (8 LDG.128 in flight -> one DRAM latency exposure); row-dots r_i/s_j
//     computed from these registers (width-8 shuffle), no separate phase.
//   per pass (BK=128): store row-major As=Xi / Bs=Xj*W2 (straight float4,
//     coalesced, STS floor), then 8 split-K groups of 64 threads compute a
//     strided 4x4 microtile (rows ig+8m, cols jg+8n): per k-quad 8 LDS.128
//     (1 wavefront each, broadcast) + 64 FFMA.
//   reduce: groups 1-7 write accs into the tile-smem overlay (stride 17);
//   epilogue (group 0): + r_i + bias + s_j + W3[j+127-a(b,i)], mask, store,
//     width-8 partial argmax -> scratch; last block decodes preds.
// ---------------------------------------------------------------------------
__global__ void __launch_bounds__(512)
pair_fused_kernel(const float* __restrict__ x,
                  const int* __restrict__ mask,
                  const float* __restrict__ W,
                  const float* __restrict__ bias,
                  float* __restrict__ out,
                  float* __restrict__ preds) {
    __shared__ __align__(16) float sm[2 * BM * RSTR];   // 8448 floats, 33.8 KB
    float* As = sm;                        // [32][RSTR] row-major
    float* Bs = sm + BM * RSTR;            // [32][RSTR] (W2 folded)
    __shared__ float rs[64];               // [0:32) r_i, [32:64) s_j

    const int t  = threadIdx.x;
    const int jt = blockIdx.x, it = blockIdx.y, bb = blockIdx.z;
    const int i0 = it * BM, j0 = jt * BN;
    const float* xb = x + bb * N_ * H_;
    const float* W2 = W + 2 * H_;

    // ---- loader geometry: row = t>>3 (0..63), 8 lanes x 16 floats ---------
    const int  lrow  = t >> 3;             // 0..63
    const int  lane8 = t & 7;
    const bool isA   = (lrow < 32);        // warp-uniform (4 rows/warp)
    const int  grow  = (isA ? i0 + lrow : j0 + (lrow - 32));

    // ---- prefetch BOTH passes + fused row-dot -----------------------------
    float4 v0[4], v1[4];
    {
        const float* src = xb + grow * H_ + lane8 * 16;
#pragma unroll
        for (int q = 0; q < 4; q++) v0[q] = ((const float4*)src)[q];
#pragma unroll
        for (int q = 0; q < 4; q++) v1[q] = ((const float4*)(src + 128))[q];

        const float* wsrc = (isA ? W : W + H_) + lane8 * 16;
        float rdot = 0.f;
#pragma unroll
        for (int q = 0; q < 4; q++) {
            float4 wv = ((const float4*)wsrc)[q];
            rdot += v0[q].x * wv.x + v0[q].y * wv.y
                  + v0[q].z * wv.z + v0[q].w * wv.w;
        }
#pragma unroll
        for (int q = 0; q < 4; q++) {
            float4 wv = ((const float4*)(wsrc + 128))[q];
            rdot += v1[q].x * wv.x + v1[q].y * wv.y
                  + v1[q].z * wv.z + v1[q].w * wv.w;
        }
        rdot += __shfl_down_sync(0xffffffffu, rdot, 1, 8);
        rdot += __shfl_down_sync(0xffffffffu, rdot, 2, 8);
        rdot += __shfl_down_sync(0xffffffffu, rdot, 4, 8);
        if (lane8 == 0) rs[lrow] = rdot;   // rs[0:32)=r_i, rs[32:64)=s_j
    }

    // ---- compute geometry: 8 split-K groups of 64 (8x8), strided 4x4 ------
    const int g  = t >> 6;                 // 0..7: k slice [g*16, g*16+16)
    const int ts = t & 63;
    const int ig = ts >> 3;                // rows ig, ig+8, ig+16, ig+24
    const int jg = ts & 7;                 // cols jg, jg+8, jg+16, jg+24

    float acc[4][4] = {};

#pragma unroll
    for (int pass = 0; pass < 2; pass++) {
        if (pass) __syncthreads();         // tile reads done before overwrite
        // ---- store tiles (row-major straight copy; W2 folded for B) -------
        {
            const float4* v = pass ? v1 : v0;
            if (isA) {
                float4* dst = (float4*)(As + lrow * RSTR + lane8 * 16);
#pragma unroll
                for (int q = 0; q < 4; q++) dst[q] = v[q];
            } else {
                const float* w2s = W2 + pass * 128 + lane8 * 16;
                float4* dst = (float4*)(Bs + (lrow - 32) * RSTR + lane8 * 16);
#pragma unroll
                for (int q = 0; q < 4; q++) {
                    float4 wv = ((const float4*)w2s)[q];
                    dst[q] = make_float4(v[q].x * wv.x, v[q].y * wv.y,
                                         v[q].z * wv.z, v[q].w * wv.w);
                }
            }
        }
        __syncthreads();

        // ---- compute: 4 k-quads of this group's 16-k slice ----------------
        const float* ab = As + g * 16;
        const float* bbp = Bs + g * 16;
#pragma unroll
        for (int kq = 0; kq < 4; kq++) {
            float4 af[4], bf[4];
#pragma unroll
            for (int m = 0; m < 4; m++)
                af[m] = *(const float4*)(ab + (ig + 8 * m) * RSTR + kq * 4);
#pragma unroll
            for (int n = 0; n < 4; n++)
                bf[n] = *(const float4*)(bbp + (jg + 8 * n) * RSTR + kq * 4);
#pragma unroll
            for (int m = 0; m < 4; m++)
#pragma unroll
                for (int n = 0; n < 4; n++)
                    acc[m][n] += af[m].x * bf[n].x + af[m].y * bf[n].y
                               + af[m].z * bf[n].z + af[m].w * bf[n].w;
        }
    }

    // ---- split-K reduction: groups 1-7 write partials into tile overlay ---
    __syncthreads();
    if (g != 0) {
        float* dst = sm + ((g - 1) * 64 + ts) * 17;   // stride 17: conflict-free
#pragma unroll
        for (int m = 0; m < 4; m++)
#pragma unroll
            for (int n = 0; n < 4; n++) dst[m * 4 + n] = acc[m][n];
    }
    __syncthreads();

    // ---- epilogue (group 0: 64 threads, 16 outputs each) ------------------
    if (g == 0) {
#pragma unroll
        for (int q = 1; q < 8; q++) {
            const float* src = sm + ((q - 1) * 64 + ts) * 17;
#pragma unroll
            for (int m = 0; m < 4; m++)
#pragma unroll
                for (int n = 0; n < 4; n++) acc[m][n] += src[m * 4 + n];
        }

        const float  b0v = bias[0];
        const float* W3 = W + 3 * H_;
        const int* mb = mask + bb * N_;

#pragma unroll
        for (int m = 0; m < 4; m++) {
            const int li = ig + 8 * m;
            const int i  = i0 + li;
            // repeat_interleave(dim=0).view quirk: one-hot row = (b*128+i)//8
            const int aidx = bb * 16 + (i >> 3);
            const float ri = rs[li] + b0v;
            const bool mi = mb[i] != 0;
            const float* w3r = W3 + 127 - aidx + j0;
            float* orow = out + (bb * N_ + i) * N_ + j0;

            float best = -CUDART_INF_F;
            int   bj   = 0;
#pragma unroll
            for (int n = 0; n < 4; n++) {
                const int jl = jg + 8 * n;            // ascending in n
                float v = acc[m][n] + ri + rs[32 + jl] + w3r[jl];
                if (!(mi && (mb[j0 + jl] != 0))) v = -CUDART_INF_F;
                orow[jl] = v;
                if (v > best) { best = v; bj = j0 + jl; }
            }
            // width-8 reduce over jg (idx-min tie-break: first occurrence)
#pragma unroll
            for (int off = 4; off; off >>= 1) {
                float ov = __shfl_down_sync(0xffffffffu, best, off, 8);
                int   oj = __shfl_down_sync(0xffffffffu, bj,   off, 8);
                if (ov > best || (ov == best && oj < bj)) { best = ov; bj = oj; }
            }
            if (jg == 0) {
                g_pval[(bb * N_ + i) * 4 + jt] = best;
                g_pidx[(bb * N_ + i) * 4 + jt] = bj;
            }
        }
    }

    // ---- last-arriving block decodes preds --------------------------------
    if (g == 0 && jg == 0) __threadfence();   // only scratch writers fence
    __syncthreads();
    __shared__ int slast;
    if (t == 0) slast = atomicAdd(&g_cnt, 1);
    __syncthreads();
    if (slast == gridDim.x * gridDim.y * gridDim.z - 1) {
        for (int r = t; r < B_ * N_; r += 512) {
            float bv = g_pval[r * 4 + 0];
            int   bj = g_pidx[r * 4 + 0];
#pragma unroll
            for (int q = 1; q < 4; q++) {
                float v = g_pval[r * 4 + q];
                if (v > bv) { bv = v; bj = g_pidx[r * 4 + q]; }  // idx grows with q
            }
            preds[r] = (float)bj;
        }
        __syncthreads();
        if (t == 0) g_cnt = 0;   // reset for next graph replay
    }
}

// ---------------------------------------------------------------------------
extern "C" void kernel_launch(void* const* d_in, const int* in_sizes, int n_in,
                              void* d_out, int out_size) {
    const float* x    = (const float*)d_in[0];   // [8,128,256] float32
    const int*   mask = (const int*)d_in[1];     // [8,128] bool -> int32
    const float* W    = (const float*)d_in[2];   // [1,1023] float32
    const float* bias = (const float*)d_in[3];   // [1] float32
    float* out = (float*)d_out;

    const int nlog = B_ * N_ * N_;               // 131072
    float* preds = out + nlog;                   // [1024] as float

    dim3 grid(N_ / BN, N_ / BM, B_);             // (4,4,8) = 128 blocks
    pair_fused_kernel<<<grid, 512>>>(x, mask, W, bias, out, preds);
}